// round 4
// baseline (speedup 1.0000x reference)
#include <cuda_runtime.h>

typedef unsigned long long u64;

// ---------------- packed fp32x2 helpers (Blackwell FFMA2 path) ----------------
__device__ __forceinline__ u64 pack_dup(float a) {
    u64 r; asm("mov.b64 %0, {%1, %1};" : "=l"(r) : "f"(a)); return r;
}
__device__ __forceinline__ void fma2(u64& c, u64 a, u64 b) {
    asm("fma.rn.f32x2 %0, %1, %2, %0;" : "+l"(c) : "l"(a), "l"(b));
}
__device__ __forceinline__ float2 unpack2(u64 v) {
    float lo, hi; asm("mov.b64 {%0, %1}, %2;" : "=f"(lo), "=f"(hi) : "l"(v));
    return make_float2(lo, hi);
}

// ---------------- problem constants ----------------
#define NB   8          // nodes per CTA
#define MCO  9
#define AA   42
#define XW   1152
#define THREADS 512

// ---------------- shared memory layout (floats) ----------------
#define S_G    0                    // 8*42*128 = 43008
#define S_B1   43008                // 72*128   = 9216
#define S_PAN  52224                // 16*256   = 4096
#define S_TG   56320                // 378
#define S_FG   (S_TG + 378)         // 378
#define S_GB   (S_FG + 378)         // 256
#define S_BB1  (S_GB + 256)         // 128
#define S_BB2  (S_BB1 + 128)        // 128
#define S_NW   (S_BB2 + 128)        // 384
#define S_RED  (S_NW + 384)         // 16 (per-warp sumsq partials)
#define SMEM_FLOATS (S_RED + 16)    // 57988 floats = 231952 bytes

// ---------------------------------------------------------------------------
// Per-degree dense 128x128 GEMM, 16 warps: warps split 128 cols into 2 halves.
// Rows r = m*8 + i grouped by degree l. Out[row][col]=sum_k W[l][col][k]*A[row][k]
// ---------------------------------------------------------------------------
__device__ __forceinline__ void gemm_degree(const float* __restrict__ A,
                                            const float* __restrict__ W,
                                            float* __restrict__ O,
                                            const float* __restrict__ bias0,
                                            float* __restrict__ s_pan)
{
    const int tid    = threadIdx.x;
    const int colgrp = (tid & 31) + ((tid >> 8) << 5);  // 0..63, covers cols 2cg,2cg+1
    const int rg     = (tid >> 5) & 7;                  // row group 0..7
    const int pcol   = tid & 127;                       // panel staging col
    const int pkq    = tid >> 7;                        // 0..3, k quartet

    const float4* wg = (const float4*)W;
    float4 pf = wg[pcol * 32 + pkq];    // tile (l=0, kt=0)

#pragma unroll
    for (int l = 0; l < 3; l++) {
        const int TR   = 2 * l + 1;
        const int base = l * l * 8;
        const float* Ar[5];
#pragma unroll
        for (int j = 0; j < 5; j++) {
            int jj = (j < TR) ? j : 0;
            Ar[j] = A + (base + rg + 8 * jj) * 128;
        }
        u64 acc[5];
#pragma unroll
        for (int j = 0; j < 5; j++) acc[j] = 0ull;

        for (int kt = 0; kt < 8; kt++) {
            __syncthreads();
            s_pan[(pkq * 4 + 0) * 128 + pcol] = pf.x;
            s_pan[(pkq * 4 + 1) * 128 + pcol] = pf.y;
            s_pan[(pkq * 4 + 2) * 128 + pcol] = pf.z;
            s_pan[(pkq * 4 + 3) * 128 + pcol] = pf.w;
            __syncthreads();

            {   // prefetch next tile
                int t = l * 8 + kt + 1;
                if (t < 24) {
                    int ll = t >> 3, ktt = t & 7;
                    pf = ((const float4*)(W + ll * 16384))[pcol * 32 + ktt * 4 + pkq];
                }
            }

            const int k0 = kt * 16;
            const u64* pan64 = (const u64*)s_pan;
#pragma unroll
            for (int kk = 0; kk < 16; kk += 2) {
                u64 w0 = pan64[(kk + 0) * 64 + colgrp];
                u64 w1 = pan64[(kk + 1) * 64 + colgrp];
#pragma unroll
                for (int j = 0; j < TR; j++) {
                    float2 a2 = *(const float2*)(Ar[j] + k0 + kk);
                    fma2(acc[j], pack_dup(a2.x), w0);
                    fma2(acc[j], pack_dup(a2.y), w1);
                }
            }
        }
        // epilogue
#pragma unroll
        for (int j = 0; j < TR; j++) {
            float2 r = unpack2(acc[j]);
            if (l == 0) {
                r.x += bias0[colgrp * 2 + 0];
                r.y += bias0[colgrp * 2 + 1];
            }
            *(float2*)(O + (base + rg + 8 * j) * 128 + colgrp * 2) = r;
        }
    }
}

// ---------------------------------------------------------------------------
// GEMM2 chunk: JR rows/thread (rows rbase+rg+16j), 8 cols/thread (4 z + 4 gate)
// ---------------------------------------------------------------------------
template <int JR>
__device__ __forceinline__ void gemm2_chunk(int rbase,
                                            float* __restrict__ s_g,
                                            const float4* __restrict__ wg4,
                                            float* __restrict__ s_pan,
                                            const float* __restrict__ s_gb)
{
    const int tid  = threadIdx.x;
    const int cg   = tid & 31;
    const int rg   = tid >> 5;        // 0..15
    const int pcol = tid & 255;
    const int pkh  = tid >> 8;        // 0..1

    const float* gr[JR];
#pragma unroll
    for (int j = 0; j < JR; j++) gr[j] = s_g + (rbase + rg + 16 * j) * 128;

    u64 aL0[JR], aL1[JR], aH0[JR], aH1[JR];
#pragma unroll
    for (int j = 0; j < JR; j++) { aL0[j] = 0ull; aL1[j] = 0ull; aH0[j] = 0ull; aH1[j] = 0ull; }

    float4 p0 = wg4[pcol * 32 + pkh * 2 + 0];
    float4 p1 = wg4[pcol * 32 + pkh * 2 + 1];

    for (int kt = 0; kt < 8; kt++) {
        __syncthreads();
        {
            const int pb = (pkh * 8) * 256 + pcol;
            s_pan[pb + 0 * 256] = p0.x; s_pan[pb + 1 * 256] = p0.y;
            s_pan[pb + 2 * 256] = p0.z; s_pan[pb + 3 * 256] = p0.w;
            s_pan[pb + 4 * 256] = p1.x; s_pan[pb + 5 * 256] = p1.y;
            s_pan[pb + 6 * 256] = p1.z; s_pan[pb + 7 * 256] = p1.w;
        }
        __syncthreads();

        if (kt < 7) {
            p0 = wg4[pcol * 32 + (kt + 1) * 4 + pkh * 2 + 0];
            p1 = wg4[pcol * 32 + (kt + 1) * 4 + pkh * 2 + 1];
        }

        const int k0 = kt * 16;
        const ulonglong2* pan2 = (const ulonglong2*)s_pan;
#pragma unroll
        for (int kk = 0; kk < 16; kk += 2) {
            ulonglong2 wloA = pan2[(kk + 0) * 64 + cg];
            ulonglong2 whiA = pan2[(kk + 0) * 64 + 32 + cg];
            ulonglong2 wloB = pan2[(kk + 1) * 64 + cg];
            ulonglong2 whiB = pan2[(kk + 1) * 64 + 32 + cg];
#pragma unroll
            for (int j = 0; j < JR; j++) {
                float2 a2 = *(const float2*)(gr[j] + k0 + kk);
                u64 ax = pack_dup(a2.x);
                u64 ay = pack_dup(a2.y);
                fma2(aL0[j], ax, wloA.x);
                fma2(aL1[j], ax, wloA.y);
                fma2(aH0[j], ax, whiA.x);
                fma2(aH1[j], ax, whiA.y);
                fma2(aL0[j], ay, wloB.x);
                fma2(aL1[j], ay, wloB.y);
                fma2(aH0[j], ay, whiB.x);
                fma2(aH1[j], ay, whiB.y);
            }
        }
    }

    const float gb0 = s_gb[cg * 4 + 0], gb1 = s_gb[cg * 4 + 1];
    const float gb2 = s_gb[cg * 4 + 2], gb3 = s_gb[cg * 4 + 3];
    const float hb0 = s_gb[128 + cg * 4 + 0], hb1 = s_gb[128 + cg * 4 + 1];
    const float hb2 = s_gb[128 + cg * 4 + 2], hb3 = s_gb[128 + cg * 4 + 3];

    // SwiGLU epilogue — each thread writes only rows it read itself.
#pragma unroll
    for (int j = 0; j < JR; j++) {
        float2 l01 = unpack2(aL0[j]), l23 = unpack2(aL1[j]);
        float2 h01 = unpack2(aH0[j]), h23 = unpack2(aH1[j]);
        float z0 = l01.x + gb0, z1 = l01.y + gb1, z2 = l23.x + gb2, z3 = l23.y + gb3;
        float g0 = h01.x + hb0, g1 = h01.y + hb1, g2v = h23.x + hb2, g3 = h23.y + hb3;
        float4 o4;
        o4.x = z0 * (1.f / (1.f + __expf(-z0))) * g0;
        o4.y = z1 * (1.f / (1.f + __expf(-z1))) * g1;
        o4.z = z2 * (1.f / (1.f + __expf(-z2))) * g2v;
        o4.w = z3 * (1.f / (1.f + __expf(-z3))) * g3;
        ((float4*)s_g)[(rbase + rg + 16 * j) * 32 + cg] = o4;
    }
}

extern "C" __global__ void __launch_bounds__(THREADS, 1)
eqffn_kernel(const float* __restrict__ x,
             const float* __restrict__ nwg,
             const float* __restrict__ w1g,
             const float* __restrict__ b1g,
             const float* __restrict__ gwg,
             const float* __restrict__ gbg,
             const float* __restrict__ w2g,
             const float* __restrict__ b2g,
             const float* __restrict__ tgg,
             const float* __restrict__ fgg,
             float* __restrict__ y,
             int N)
{
    extern __shared__ float sm[];
    float* s_g   = sm + S_G;
    float* s_h1  = sm + S_B1;
    float* s_pan = sm + S_PAN;
    float* s_tg  = sm + S_TG;
    float* s_fg  = sm + S_FG;
    float* s_gb  = sm + S_GB;
    float* s_bb1 = sm + S_BB1;
    float* s_bb2 = sm + S_BB2;
    float* s_nw  = sm + S_NW;
    float* s_red = sm + S_RED;

    const int tid  = threadIdx.x;
    const int lane = tid & 31;
    const int wrp  = tid >> 5;        // 0..15
    const int nodl = wrp >> 1;        // node-within-block 0..7
    const int half = wrp & 1;

    // small constants -> smem
    for (int i = tid; i < 378; i += THREADS) s_tg[i] = tgg[i];
    for (int i = tid; i < 378; i += THREADS) s_fg[i] = fgg[i];
    if (tid < 256) s_gb[tid] = gbg[tid];
    if (tid < 128) { s_bb1[tid] = b1g[tid]; s_bb2[tid] = b2g[tid]; }
    if (tid < 384) s_nw[tid] = nwg[tid];

    const int node = blockIdx.x * NB + nodl;
    const bool valid = node < N;

    // ---------- Phase 0: load x (half row per warp), sumsq, pack + RMS-norm ----------
    float v[18];
    float ss = 0.f;
    if (valid) {
        const float* xr = x + (size_t)node * XW + half * 576;
#pragma unroll
        for (int k = 0; k < 18; k++) { v[k] = xr[lane + 32 * k]; ss += v[k] * v[k]; }
    } else {
#pragma unroll
        for (int k = 0; k < 18; k++) v[k] = 0.f;
    }
#pragma unroll
    for (int o = 16; o; o >>= 1) ss += __shfl_xor_sync(0xffffffffu, ss, o);
    if (lane == 0) s_red[wrp] = ss;
    __syncthreads();   // s_red + s_nw ready
    const float sst = s_red[nodl * 2] + s_red[nodl * 2 + 1];
    const float rinv = rsqrtf(sst * (1.0f / 1152.0f) + 1e-6f);

#pragma unroll
    for (int k = 0; k < 18; k++) {
        int j = half * 576 + lane + 32 * k;
        int l, coeff, c;
        if (j < 128)      { l = 0; coeff = 0; c = j; }
        else if (j < 512) { l = 1; int q = j - 128; c = q / 3; coeff = 1 + (q - 3 * c); }
        else              { l = 2; int q = j - 512; c = q / 5; coeff = 4 + (q - 5 * c); }
        s_g[(coeff * NB + nodl) * 128 + c] = v[k] * rinv * s_nw[l * 128 + c];
    }
    __syncthreads();

    // ---------- Phase 1: GEMM1 ----------
    gemm_degree(s_g, w1g, s_h1, s_bb1, s_pan);
    __syncthreads();

    // ---------- Phase 2: to_grid  (each warp: one node, 21 grid points) ----------
    {
        float4 h1r[MCO];
#pragma unroll
        for (int m = 0; m < MCO; m++)
            h1r[m] = ((const float4*)s_h1)[(m * NB + nodl) * 32 + lane];
        const int a0 = half * 21;
        for (int a = a0; a < a0 + 21; a++) {
            float4 acc = make_float4(0.f, 0.f, 0.f, 0.f);
#pragma unroll
            for (int m = 0; m < MCO; m++) {
                float t = s_tg[a * MCO + m];
                acc.x += t * h1r[m].x; acc.y += t * h1r[m].y;
                acc.z += t * h1r[m].z; acc.w += t * h1r[m].w;
            }
            ((float4*)s_g)[(nodl * AA + a) * 32 + lane] = acc;
        }
    }
    __syncthreads();

    // ---------- Phase 3+4: GEMM2 (336x256x128) + SwiGLU ----------
    {
        const float4* wg4 = (const float4*)gwg;
        gemm2_chunk<6>(0,   s_g, wg4, s_pan, s_gb);
        gemm2_chunk<6>(96,  s_g, wg4, s_pan, s_gb);
        gemm2_chunk<6>(192, s_g, wg4, s_pan, s_gb);
        gemm2_chunk<3>(288, s_g, wg4, s_pan, s_gb);
    }
    __syncthreads();

    // ---------- Phase 5: from_grid (warp: one node, half the m's) ----------
    {
        const int m0   = half ? 5 : 0;
        const int mcnt = half ? 4 : 5;
        float4 acc[5];
#pragma unroll
        for (int m = 0; m < 5; m++) acc[m] = make_float4(0.f, 0.f, 0.f, 0.f);
        for (int a = 0; a < AA; a++) {
            float4 g4 = ((const float4*)s_g)[(nodl * AA + a) * 32 + lane];
#pragma unroll
            for (int m = 0; m < 5; m++) {
                if (m < mcnt) {
                    float f = s_fg[(m0 + m) * AA + a];
                    acc[m].x += f * g4.x; acc[m].y += f * g4.y;
                    acc[m].z += f * g4.z; acc[m].w += f * g4.w;
                }
            }
        }
#pragma unroll
        for (int m = 0; m < 5; m++)
            if (m < mcnt)
                ((float4*)s_h1)[((m0 + m) * NB + nodl) * 32 + lane] = acc[m];
    }
    __syncthreads();

    // ---------- Phase 6: GEMM3 ----------
    gemm_degree(s_h1, w2g, s_g, s_bb2, s_pan);
    __syncthreads();

    // ---------- Phase 7: unpack + store ----------
    if (valid) {
        float* yr = y + (size_t)node * XW;
#pragma unroll
        for (int k = 0; k < 18; k++) {
            int j = half * 576 + lane + 32 * k;
            int coeff, c;
            if (j < 128)      { coeff = 0; c = j; }
            else if (j < 512) { int q = j - 128; c = q / 3; coeff = 1 + (q - 3 * c); }
            else              { int q = j - 512; c = q / 5; coeff = 4 + (q - 5 * c); }
            yr[j] = s_g[(coeff * NB + nodl) * 128 + c];
        }
    }
}

extern "C" void kernel_launch(void* const* d_in, const int* in_sizes, int n_in,
                              void* d_out, int out_size)
{
    const float* x   = (const float*)d_in[0];
    const float* nw  = (const float*)d_in[1];
    const float* w1  = (const float*)d_in[2];
    const float* b1  = (const float*)d_in[3];
    const float* gw  = (const float*)d_in[4];
    const float* gb  = (const float*)d_in[5];
    const float* w2  = (const float*)d_in[6];
    const float* b2  = (const float*)d_in[7];
    const float* tg  = (const float*)d_in[8];
    const float* fg  = (const float*)d_in[9];
    float* y = (float*)d_out;

    const int N = in_sizes[0] / XW;
    const int smem_bytes = SMEM_FLOATS * 4;
    cudaFuncSetAttribute(eqffn_kernel, cudaFuncAttributeMaxDynamicSharedMemorySize, smem_bytes);
    const int grid = (N + NB - 1) / NB;
    eqffn_kernel<<<grid, THREADS, smem_bytes>>>(x, nw, w1, b1, gw, gb, w2, b2, tg, fg, y, N);
}

// round 8
// speedup vs baseline: 1.2545x; 1.2545x over previous
#include <cuda_runtime.h>
#include <cuda_bf16.h>

typedef unsigned long long u64;
typedef unsigned int u32;

// ---------------- packed fp32x2 helpers (FFMA2 path for GEMM1/3) ----------------
__device__ __forceinline__ u64 pack_dup(float a) {
    u64 r; asm("mov.b64 %0, {%1, %1};" : "=l"(r) : "f"(a)); return r;
}
__device__ __forceinline__ void fma2(u64& c, u64 a, u64 b) {
    asm("fma.rn.f32x2 %0, %1, %2, %0;" : "+l"(c) : "l"(a), "l"(b));
}
__device__ __forceinline__ float2 unpack2(u64 v) {
    float lo, hi; asm("mov.b64 {%0, %1}, %2;" : "=f"(lo), "=f"(hi) : "l"(v));
    return make_float2(lo, hi);
}

// ---------------- mma.sync bf16 helpers ----------------
__device__ __forceinline__ u32 prmt(u32 a, u32 b, u32 s) {
    u32 d; asm("prmt.b32 %0, %1, %2, %3;" : "=r"(d) : "r"(a), "r"(b), "r"(s));
    return d;
}
__device__ __forceinline__ void mma_bf16(float4& c, u32 a0, u32 a1, u32 a2, u32 a3,
                                         u32 b0, u32 b1) {
    asm("mma.sync.aligned.m16n8k16.row.col.f32.bf16.bf16.f32 "
        "{%0,%1,%2,%3}, {%4,%5,%6,%7}, {%8,%9}, {%0,%1,%2,%3};"
        : "+f"(c.x), "+f"(c.y), "+f"(c.z), "+f"(c.w)
        : "r"(a0), "r"(a1), "r"(a2), "r"(a3), "r"(b0), "r"(b1));
}
// fp32 -> {bf16 hi (low16), bf16 lo (high16)} packed u32
__device__ __forceinline__ u32 pack_hl(float a) {
    __nv_bfloat16 hb = __float2bfloat16_rn(a);
    float r = a - __bfloat162float(hb);
    __nv_bfloat16 lb = __float2bfloat16_rn(r);
    return (u32)__bfloat16_as_ushort(hb) | ((u32)__bfloat16_as_ushort(lb) << 16);
}

// ---------------- problem constants ----------------
#define NB   8
#define MCO  9
#define AA   42
#define XW   1152
#define THREADS 512

// ---------------- shared memory layout (floats) ----------------
#define S_G    0                    // 336*128 fp32 / packed-u32 (g -> A packed -> gg)
#define S_B1   43008                // 72*128 (h1/h2) ; GEMM2 B buffers alias this (8192 u32)
#define S_PAN  52224                // 16*256 (GEMM1/3 panel)
#define S_TG   56320
#define S_FG   (S_TG + 378)
#define S_GB   (S_FG + 378)
#define S_BB1  (S_GB + 256)
#define S_BB2  (S_BB1 + 128)
#define S_NW   (S_BB2 + 128)
#define S_RED  (S_NW + 384)
#define SMEM_FLOATS (S_RED + 16)

// ---------------------------------------------------------------------------
// GEMM1/GEMM3: per-degree dense 128x128, FFMA2 (unchanged, passing path)
// ---------------------------------------------------------------------------
__device__ __forceinline__ void gemm_degree(const float* __restrict__ A,
                                            const float* __restrict__ W,
                                            float* __restrict__ O,
                                            const float* __restrict__ bias0,
                                            float* __restrict__ s_pan)
{
    const int tid    = threadIdx.x;
    const int colgrp = (tid & 31) + ((tid >> 8) << 5);
    const int rg     = (tid >> 5) & 7;
    const int pcol   = tid & 127;
    const int pkq    = tid >> 7;

    const float4* wg = (const float4*)W;
    float4 pf = wg[pcol * 32 + pkq];

#pragma unroll
    for (int l = 0; l < 3; l++) {
        const int TR   = 2 * l + 1;
        const int base = l * l * 8;
        const float* Ar[5];
#pragma unroll
        for (int j = 0; j < 5; j++) {
            int jj = (j < TR) ? j : 0;
            Ar[j] = A + (base + rg + 8 * jj) * 128;
        }
        u64 acc[5];
#pragma unroll
        for (int j = 0; j < 5; j++) acc[j] = 0ull;

        for (int kt = 0; kt < 8; kt++) {
            __syncthreads();
            s_pan[(pkq * 4 + 0) * 128 + pcol] = pf.x;
            s_pan[(pkq * 4 + 1) * 128 + pcol] = pf.y;
            s_pan[(pkq * 4 + 2) * 128 + pcol] = pf.z;
            s_pan[(pkq * 4 + 3) * 128 + pcol] = pf.w;
            __syncthreads();
            {
                int t = l * 8 + kt + 1;
                if (t < 24) {
                    int ll = t >> 3, ktt = t & 7;
                    pf = ((const float4*)(W + ll * 16384))[pcol * 32 + ktt * 4 + pkq];
                }
            }
            const int k0 = kt * 16;
            const u64* pan64 = (const u64*)s_pan;
#pragma unroll
            for (int kk = 0; kk < 16; kk += 2) {
                u64 w0 = pan64[(kk + 0) * 64 + colgrp];
                u64 w1 = pan64[(kk + 1) * 64 + colgrp];
#pragma unroll
                for (int j = 0; j < TR; j++) {
                    float2 a2 = *(const float2*)(Ar[j] + k0 + kk);
                    fma2(acc[j], pack_dup(a2.x), w0);
                    fma2(acc[j], pack_dup(a2.y), w1);
                }
            }
        }
#pragma unroll
        for (int j = 0; j < TR; j++) {
            float2 r = unpack2(acc[j]);
            if (l == 0) {
                r.x += bias0[colgrp * 2 + 0];
                r.y += bias0[colgrp * 2 + 1];
            }
            *(float2*)(O + (base + rg + 8 * j) * 128 + colgrp * 2) = r;
        }
    }
}

// Stage one 16-k chunk of grid_w into hi/lo bf16-pair planes, kpair-permuted so
// that LDS.64 at (n, 2*(lane&3)) yields {b0, b1} fragments directly.
__device__ __forceinline__ void stage_chunk(const float* __restrict__ gwg,
                                            u32* __restrict__ buf, int c, int tid)
{
#pragma unroll
    for (int p = tid; p < 2048; p += THREADS) {
        int n = p >> 3, j = p & 7;
        float2 w = *(const float2*)(gwg + n * 128 + c * 16 + 2 * j);
        __nv_bfloat16 h0 = __float2bfloat16_rn(w.x);
        __nv_bfloat16 h1 = __float2bfloat16_rn(w.y);
        float r0 = w.x - __bfloat162float(h0);
        float r1 = w.y - __bfloat162float(h1);
        __nv_bfloat16 l0 = __float2bfloat16_rn(r0);
        __nv_bfloat16 l1 = __float2bfloat16_rn(r1);
        u32 hiw = (u32)__bfloat16_as_ushort(h0) | ((u32)__bfloat16_as_ushort(h1) << 16);
        u32 low = (u32)__bfloat16_as_ushort(l0) | ((u32)__bfloat16_as_ushort(l1) << 16);
        int pos = 2 * (j & 3) + (j >> 2);   // interleave so (j, j+4) are adjacent
        buf[n * 8 + pos] = hiw;
        buf[2048 + n * 8 + pos] = low;
    }
}

extern "C" __global__ void __launch_bounds__(THREADS, 1)
eqffn_kernel(const float* __restrict__ x,
             const float* __restrict__ nwg,
             const float* __restrict__ w1g,
             const float* __restrict__ b1g,
             const float* __restrict__ gwg,
             const float* __restrict__ gbg,
             const float* __restrict__ w2g,
             const float* __restrict__ b2g,
             const float* __restrict__ tgg,
             const float* __restrict__ fgg,
             float* __restrict__ y,
             int N)
{
    extern __shared__ __align__(16) float sm[];
    float* s_g   = sm + S_G;
    float* s_h1  = sm + S_B1;
    float* s_pan = sm + S_PAN;
    float* s_tg  = sm + S_TG;
    float* s_fg  = sm + S_FG;
    float* s_gb  = sm + S_GB;
    float* s_bb1 = sm + S_BB1;
    float* s_bb2 = sm + S_BB2;
    float* s_nw  = sm + S_NW;
    float* s_red = sm + S_RED;

    const int tid  = threadIdx.x;
    const int lane = tid & 31;
    const int wrp  = tid >> 5;
    const int nodl = wrp >> 1;
    const int half = wrp & 1;

    for (int i = tid; i < 378; i += THREADS) s_tg[i] = tgg[i];
    for (int i = tid; i < 378; i += THREADS) s_fg[i] = fgg[i];
    if (tid < 256) s_gb[tid] = gbg[tid];
    if (tid < 128) { s_bb1[tid] = b1g[tid]; s_bb2[tid] = b2g[tid]; }
    if (tid < 384) s_nw[tid] = nwg[tid];

    const int node = blockIdx.x * NB + nodl;
    const bool valid = node < N;

    // ---------- Phase 0: load x, sumsq, pack + RMS-norm ----------
    float v[18];
    float ss = 0.f;
    if (valid) {
        const float* xr = x + (size_t)node * XW + half * 576;
#pragma unroll
        for (int k = 0; k < 18; k++) { v[k] = xr[lane + 32 * k]; ss += v[k] * v[k]; }
    } else {
#pragma unroll
        for (int k = 0; k < 18; k++) v[k] = 0.f;
    }
#pragma unroll
    for (int o = 16; o; o >>= 1) ss += __shfl_xor_sync(0xffffffffu, ss, o);
    if (lane == 0) s_red[wrp] = ss;
    __syncthreads();
    const float sst = s_red[nodl * 2] + s_red[nodl * 2 + 1];
    const float rinv = rsqrtf(sst * (1.0f / 1152.0f) + 1e-6f);

#pragma unroll
    for (int k = 0; k < 18; k++) {
        int j = half * 576 + lane + 32 * k;
        int l, coeff, c;
        if (j < 128)      { l = 0; coeff = 0; c = j; }
        else if (j < 512) { l = 1; int q = j - 128; c = q / 3; coeff = 1 + (q - 3 * c); }
        else              { l = 2; int q = j - 512; c = q / 5; coeff = 4 + (q - 5 * c); }
        s_g[(coeff * NB + nodl) * 128 + c] = v[k] * rinv * s_nw[l * 128 + c];
    }
    __syncthreads();

    // ---------- Phase 1: GEMM1 ----------
    gemm_degree(s_g, w1g, s_h1, s_bb1, s_pan);
    __syncthreads();

    // ---------- Phase 2: to_grid ----------
    {
        float4 h1r[MCO];
#pragma unroll
        for (int m = 0; m < MCO; m++)
            h1r[m] = ((const float4*)s_h1)[(m * NB + nodl) * 32 + lane];
        const int a0 = half * 21;
        for (int a = a0; a < a0 + 21; a++) {
            float4 acc = make_float4(0.f, 0.f, 0.f, 0.f);
#pragma unroll
            for (int m = 0; m < MCO; m++) {
                float t = s_tg[a * MCO + m];
                acc.x += t * h1r[m].x; acc.y += t * h1r[m].y;
                acc.z += t * h1r[m].z; acc.w += t * h1r[m].w;
            }
            ((float4*)s_g)[(nodl * AA + a) * 32 + lane] = acc;
        }
    }
    __syncthreads();

    // ---------- Phase 3+4: GEMM2 (336x256x128) via mma.sync bf16 3-pass + SwiGLU ----------
    {
        u32* sgu  = (u32*)s_g;
        u32* bbuf = (u32*)s_h1;          // two 4096-u32 buffers (32 KB)

        // A: in-place fp32 -> packed {bf16 hi | bf16 lo}
        for (int i = tid; i < 10752; i += THREADS) {
            float4 a4 = ((const float4*)s_g)[i];
            uint4 o4;
            o4.x = pack_hl(a4.x); o4.y = pack_hl(a4.y);
            o4.z = pack_hl(a4.z); o4.w = pack_hl(a4.w);
            ((uint4*)s_g)[i] = o4;
        }
        stage_chunk(gwg, bbuf, 0, tid);
        __syncthreads();

        const int rt = (wrp < 14) ? (wrp % 7) : 0;
        const int ch = (wrp < 14) ? (wrp / 7) : 0;
        const int rr = rt * 16 + (lane >> 2);     // row within block (+8 for upper)
        const int ks = (lane & 3) * 2;            // k offset within 16-chunk

        for (int b = 0; b < 3; b++) {
            const int rbase = b * 112;
            float4 c[16];
#pragma unroll
            for (int i = 0; i < 16; i++) c[i] = make_float4(0.f, 0.f, 0.f, 0.f);

            for (int kc = 0; kc < 8; kc++) {
                // prefetch next chunk (next block's chunk 0 at kc==7)
                if (kc < 7)            stage_chunk(gwg, bbuf + ((kc + 1) & 1) * 4096, kc + 1, tid);
                else if (b < 2)        stage_chunk(gwg, bbuf, 0, tid);

                if (wrp < 14) {
                    const u32* Ar = sgu + (rbase + rr) * 128 + kc * 16 + ks;
                    u64 L0 = *(const u64*)(Ar);
                    u64 L1 = *(const u64*)(Ar + 8 * 128);
                    u64 L2 = *(const u64*)(Ar + 8);
                    u64 L3 = *(const u64*)(Ar + 8 * 128 + 8);
                    u32 p0, p1;
                    u32 ah0, ah1, ah2, ah3, al0, al1, al2, al3;
                    p0 = (u32)L0; p1 = (u32)(L0 >> 32);
                    ah0 = prmt(p0, p1, 0x5410); al0 = prmt(p0, p1, 0x7632);
                    p0 = (u32)L1; p1 = (u32)(L1 >> 32);
                    ah1 = prmt(p0, p1, 0x5410); al1 = prmt(p0, p1, 0x7632);
                    p0 = (u32)L2; p1 = (u32)(L2 >> 32);
                    ah2 = prmt(p0, p1, 0x5410); al2 = prmt(p0, p1, 0x7632);
                    p0 = (u32)L3; p1 = (u32)(L3 >> 32);
                    ah3 = prmt(p0, p1, 0x5410); al3 = prmt(p0, p1, 0x7632);

                    const u32* bu = bbuf + (kc & 1) * 4096;
                    const int jsel2 = 2 * (lane & 3);
#pragma unroll
                    for (int i = 0; i < 16; i++) {
                        const int nt = (i < 8) ? (ch * 8 + i) : (16 + ch * 8 + (i - 8));
                        const int n  = nt * 8 + (lane >> 2);
                        u64 H = *(const u64*)(bu + n * 8 + jsel2);
                        u64 L = *(const u64*)(bu + 2048 + n * 8 + jsel2);
                        u32 bh0 = (u32)H, bh1 = (u32)(H >> 32);
                        u32 bl0 = (u32)L, bl1 = (u32)(L >> 32);
                        mma_bf16(c[i], ah0, ah1, ah2, ah3, bh0, bh1);
                        mma_bf16(c[i], ah0, ah1, ah2, ah3, bl0, bl1);
                        mma_bf16(c[i], al0, al1, al2, al3, bh0, bh1);
                    }
                }
                __syncthreads();
            }

            // SwiGLU epilogue: c[i] = z (cols ch*64+i*8..), c[i+8] = gate
            if (wrp < 14) {
                const int r0 = rbase + rr;
#pragma unroll
                for (int i = 0; i < 8; i++) {
                    const int h0 = ch * 64 + i * 8 + (lane & 3) * 2;
                    const float bz0 = s_gb[h0], bz1 = s_gb[h0 + 1];
                    const float bg0 = s_gb[128 + h0], bg1 = s_gb[128 + h0 + 1];
                    float4 z4 = c[i], g4 = c[i + 8];
                    float z0 = z4.x + bz0, z1 = z4.y + bz1;
                    float z2 = z4.z + bz0, z3 = z4.w + bz1;
                    float g0 = g4.x + bg0, g1 = g4.y + bg1;
                    float g2 = g4.z + bg0, g3 = g4.w + bg1;
                    float2 o01, o23;
                    o01.x = z0 * (1.f / (1.f + __expf(-z0))) * g0;
                    o01.y = z1 * (1.f / (1.f + __expf(-z1))) * g1;
                    o23.x = z2 * (1.f / (1.f + __expf(-z2))) * g2;
                    o23.y = z3 * (1.f / (1.f + __expf(-z3))) * g3;
                    *(float2*)(s_g + r0 * 128 + h0) = o01;
                    *(float2*)(s_g + (r0 + 8) * 128 + h0) = o23;
                }
            }
        }
    }
    __syncthreads();

    // ---------- Phase 5: from_grid ----------
    {
        const int m0   = half ? 5 : 0;
        const int mcnt = half ? 4 : 5;
        float4 acc[5];
#pragma unroll
        for (int m = 0; m < 5; m++) acc[m] = make_float4(0.f, 0.f, 0.f, 0.f);
        for (int a = 0; a < AA; a++) {
            float4 g4 = ((const float4*)s_g)[(nodl * AA + a) * 32 + lane];
#pragma unroll
            for (int m = 0; m < 5; m++) {
                if (m < mcnt) {
                    float f = s_fg[(m0 + m) * AA + a];
                    acc[m].x += f * g4.x; acc[m].y += f * g4.y;
                    acc[m].z += f * g4.z; acc[m].w += f * g4.w;
                }
            }
        }
#pragma unroll
        for (int m = 0; m < 5; m++)
            if (m < mcnt)
                ((float4*)s_h1)[((m0 + m) * NB + nodl) * 32 + lane] = acc[m];
    }
    __syncthreads();

    // ---------- Phase 6: GEMM3 ----------
    gemm_degree(s_h1, w2g, s_g, s_bb2, s_pan);
    __syncthreads();

    // ---------- Phase 7: unpack + store ----------
    if (valid) {
        float* yr = y + (size_t)node * XW;
#pragma unroll
        for (int k = 0; k < 18; k++) {
            int j = half * 576 + lane + 32 * k;
            int coeff, c;
            if (j < 128)      { coeff = 0; c = j; }
            else if (j < 512) { int q = j - 128; c = q / 3; coeff = 1 + (q - 3 * c); }
            else              { int q = j - 512; c = q / 5; coeff = 4 + (q - 5 * c); }
            yr[j] = s_g[(coeff * NB + nodl) * 128 + c];
        }
    }
}

extern "C" void kernel_launch(void* const* d_in, const int* in_sizes, int n_in,
                              void* d_out, int out_size)
{
    const float* x   = (const float*)d_in[0];
    const float* nw  = (const float*)d_in[1];
    const float* w1  = (const float*)d_in[2];
    const float* b1  = (const float*)d_in[3];
    const float* gw  = (const float*)d_in[4];
    const float* gb  = (const float*)d_in[5];
    const float* w2  = (const float*)d_in[6];
    const float* b2  = (const float*)d_in[7];
    const float* tg  = (const float*)d_in[8];
    const float* fg  = (const float*)d_in[9];
    float* y = (float*)d_out;

    const int N = in_sizes[0] / XW;
    const int smem_bytes = SMEM_FLOATS * 4;
    cudaFuncSetAttribute(eqffn_kernel, cudaFuncAttributeMaxDynamicSharedMemorySize, smem_bytes);
    const int grid = (N + NB - 1) / NB;
    eqffn_kernel<<<grid, THREADS, smem_bytes>>>(x, nw, w1, b1, gw, gb, w2, b2, tg, fg, y, N);
}

// round 9
// speedup vs baseline: 1.6429x; 1.3096x over previous
#include <cuda_runtime.h>
#include <cuda_bf16.h>

typedef unsigned long long u64;
typedef unsigned int u32;

// ---------------- mma.sync bf16 helpers ----------------
__device__ __forceinline__ u32 prmt(u32 a, u32 b, u32 s) {
    u32 d; asm("prmt.b32 %0, %1, %2, %3;" : "=r"(d) : "r"(a), "r"(b), "r"(s));
    return d;
}
__device__ __forceinline__ void mma_bf16(float4& c, u32 a0, u32 a1, u32 a2, u32 a3,
                                         u32 b0, u32 b1) {
    asm("mma.sync.aligned.m16n8k16.row.col.f32.bf16.bf16.f32 "
        "{%0,%1,%2,%3}, {%4,%5,%6,%7}, {%8,%9}, {%0,%1,%2,%3};"
        : "+f"(c.x), "+f"(c.y), "+f"(c.z), "+f"(c.w)
        : "r"(a0), "r"(a1), "r"(a2), "r"(a3), "r"(b0), "r"(b1));
}
// fp32 -> {bf16 hi (low16), bf16 lo (high16)} packed u32
__device__ __forceinline__ u32 pack_hl(float a) {
    __nv_bfloat16 hb = __float2bfloat16_rn(a);
    float r = a - __bfloat162float(hb);
    __nv_bfloat16 lb = __float2bfloat16_rn(r);
    return (u32)__bfloat16_as_ushort(hb) | ((u32)__bfloat16_as_ushort(lb) << 16);
}
// float2 -> hi-pair u32 {h0|h1}, lo-pair u32 {l0|l1}
__device__ __forceinline__ void split_pair(float2 w, u32& hiw, u32& low) {
    __nv_bfloat16 h0 = __float2bfloat16_rn(w.x);
    __nv_bfloat16 h1 = __float2bfloat16_rn(w.y);
    float r0 = w.x - __bfloat162float(h0);
    float r1 = w.y - __bfloat162float(h1);
    __nv_bfloat16 l0 = __float2bfloat16_rn(r0);
    __nv_bfloat16 l1 = __float2bfloat16_rn(r1);
    hiw = (u32)__bfloat16_as_ushort(h0) | ((u32)__bfloat16_as_ushort(h1) << 16);
    low = (u32)__bfloat16_as_ushort(l0) | ((u32)__bfloat16_as_ushort(l1) << 16);
}

// ---------------- problem constants ----------------
#define NB   8
#define MCO  9
#define AA   42
#define XW   1152
#define THREADS 512

// ---------------- prepacked weights (filled by prep_kernel) ----------------
// grid_w: [8 kc][hi:2048 | lo:2048] u32, n=0..255, pos=0..7
__device__ u32 g_gw_pack[8 * 4096];
// w1/w2: [8 kc][hi:3072 | lo:3072] u32, n = deg*128+h = 0..383
__device__ u32 g_w1_pack[8 * 6144];
__device__ u32 g_w2_pack[8 * 6144];

// ---------------- shared memory layout (floats) ----------------
#define S_G    0                    // 336*128 (g/gg/out; rows 80+ alias W staging for GEMM1/3)
#define S_B1   43008                // 72*128 (h1/h2); GEMM2 B staging aliases (8192 u32)
#define S_PAN  52224                // spare
#define S_TG   56320
#define S_FG   (S_TG + 378)
#define S_GB   (S_FG + 378)
#define S_BB1  (S_GB + 256)
#define S_BB2  (S_BB1 + 128)
#define S_NW   (S_BB2 + 128)
#define S_RED  (S_NW + 384)
#define SMEM_FLOATS (S_RED + 16)

// ---------------- prep kernel: convert weights once ----------------
extern "C" __global__ void prep_kernel(const float* __restrict__ gw,
                                       const float* __restrict__ w1,
                                       const float* __restrict__ w2)
{
    const int t = blockIdx.x * blockDim.x + threadIdx.x;
    const int stride = gridDim.x * blockDim.x;
    for (int p = t; p < 16384; p += stride) {
        int n = p >> 6, kc = (p >> 3) & 7, j = p & 7;
        float2 w = *(const float2*)(gw + n * 128 + kc * 16 + 2 * j);
        u32 hiw, low; split_pair(w, hiw, low);
        int pos = 2 * (j & 3) + (j >> 2);
        g_gw_pack[kc * 4096 + n * 8 + pos] = hiw;
        g_gw_pack[kc * 4096 + 2048 + n * 8 + pos] = low;
    }
    for (int p = t; p < 24576; p += stride) {
        int n = p >> 6, kc = (p >> 3) & 7, j = p & 7;
        int pos = 2 * (j & 3) + (j >> 2);
        {
            float2 w = *(const float2*)(w1 + n * 128 + kc * 16 + 2 * j);
            u32 hiw, low; split_pair(w, hiw, low);
            g_w1_pack[kc * 6144 + n * 8 + pos] = hiw;
            g_w1_pack[kc * 6144 + 3072 + n * 8 + pos] = low;
        }
        {
            float2 w = *(const float2*)(w2 + n * 128 + kc * 16 + 2 * j);
            u32 hiw, low; split_pair(w, hiw, low);
            g_w2_pack[kc * 6144 + n * 8 + pos] = hiw;
            g_w2_pack[kc * 6144 + 3072 + n * 8 + pos] = low;
        }
    }
}

// ---------------- in-place fp32 -> packed {hi|lo} u32 ----------------
__device__ __forceinline__ void packA(float* buf, int nwords4, int tid) {
    for (int p = tid; p < nwords4; p += THREADS) {
        float4 a4 = ((const float4*)buf)[p];
        uint4 o4;
        o4.x = pack_hl(a4.x); o4.y = pack_hl(a4.y);
        o4.z = pack_hl(a4.z); o4.w = pack_hl(a4.w);
        ((uint4*)buf)[p] = o4;
    }
}

// ---------------- GEMM1/GEMM3: per-degree 72x128x128 via mma.sync ----------------
// Apk: packed A (72 rows x 128 u32, rows m*8+i grouped by degree; rows 72..79 read as pad)
// wpk: prepacked weights [8][6144]; O: fp32 out 72x128; wbuf: smem staging 2*6144 u32
__device__ __forceinline__ void gemm_degree_mma(const u32* __restrict__ Apk,
                                                const u32* __restrict__ wpk,
                                                float* __restrict__ O,
                                                const float* __restrict__ bias0,
                                                u32* __restrict__ wbuf)
{
    const int tid  = threadIdx.x;
    const int lane = tid & 31;
    const int wrp  = tid >> 5;

    // stage chunk 0
    for (int p = tid; p < 1536; p += THREADS)
        ((uint4*)wbuf)[p] = ((const uint4*)wpk)[p];
    __syncthreads();

    const int tile = (wrp < 12) ? (wrp >> 1) : 0;
    const int nh   = wrp & 1;
    int trow, tval, tdeg;
    if (tile == 0)      { trow = 0;                 tval = 8;                  tdeg = 0; }
    else if (tile <= 2) { trow = 8 + 16 * (tile - 1);  tval = (tile == 1) ? 16 : 8;  tdeg = 1; }
    else                { trow = 32 + 16 * (tile - 3); tval = (tile == 5) ? 8 : 16;  tdeg = 2; }

    float4 c[8];
#pragma unroll
    for (int i = 0; i < 8; i++) c[i] = make_float4(0.f, 0.f, 0.f, 0.f);

    const int r0 = trow + (lane >> 2);
    const u32* Ar = Apk + r0 * 128 + (lane & 3) * 2;
    const int bbase = (tdeg * 128 + nh * 64) * 8 + 2 * (lane & 3);

    for (int kc = 0; kc < 8; kc++) {
        if (kc < 7) {
            const uint4* src = (const uint4*)(wpk + (kc + 1) * 6144);
            uint4* dst = (uint4*)(wbuf + ((kc + 1) & 1) * 6144);
            for (int p = tid; p < 1536; p += THREADS) dst[p] = src[p];
        }
        if (wrp < 12) {
            const u32* a = Ar + kc * 16;
            u64 L0 = *(const u64*)(a);
            u64 L1 = *(const u64*)(a + 8 * 128);
            u64 L2 = *(const u64*)(a + 8);
            u64 L3 = *(const u64*)(a + 8 * 128 + 8);
            u32 ah0, ah1, ah2, ah3, al0, al1, al2, al3;
            { u32 p0 = (u32)L0, p1 = (u32)(L0 >> 32); ah0 = prmt(p0, p1, 0x5410); al0 = prmt(p0, p1, 0x7632); }
            { u32 p0 = (u32)L1, p1 = (u32)(L1 >> 32); ah1 = prmt(p0, p1, 0x5410); al1 = prmt(p0, p1, 0x7632); }
            { u32 p0 = (u32)L2, p1 = (u32)(L2 >> 32); ah2 = prmt(p0, p1, 0x5410); al2 = prmt(p0, p1, 0x7632); }
            { u32 p0 = (u32)L3, p1 = (u32)(L3 >> 32); ah3 = prmt(p0, p1, 0x5410); al3 = prmt(p0, p1, 0x7632); }

            const u32* bu = wbuf + (kc & 1) * 6144 + bbase;
#pragma unroll
            for (int i = 0; i < 8; i++) {
                const int noff = (i * 8 + (lane >> 2)) * 8;
                u64 H = *(const u64*)(bu + noff);
                u64 L = *(const u64*)(bu + 3072 + noff);
                u32 bh0 = (u32)H, bh1 = (u32)(H >> 32);
                u32 bl0 = (u32)L, bl1 = (u32)(L >> 32);
                mma_bf16(c[i], ah0, ah1, ah2, ah3, bh0, bh1);
                mma_bf16(c[i], ah0, ah1, ah2, ah3, bl0, bl1);
                mma_bf16(c[i], al0, al1, al2, al3, bh0, bh1);
            }
        }
        __syncthreads();
    }

    if (wrp < 12) {
        const bool wr0 = (lane >> 2) < tval;
        const bool wr1 = (lane >> 2) + 8 < tval;
#pragma unroll
        for (int i = 0; i < 8; i++) {
            const int col = nh * 64 + i * 8 + 2 * (lane & 3);
            float2 o0 = make_float2(c[i].x, c[i].y);
            float2 o1 = make_float2(c[i].z, c[i].w);
            if (tile == 0) {
                float b0 = bias0[col], b1 = bias0[col + 1];
                o0.x += b0; o0.y += b1;
                o1.x += b0; o1.y += b1;
            }
            if (wr0) *(float2*)(O + r0 * 128 + col) = o0;
            if (wr1) *(float2*)(O + (r0 + 8) * 128 + col) = o1;
        }
    }
}

extern "C" __global__ void __launch_bounds__(THREADS, 1)
eqffn_kernel(const float* __restrict__ x,
             const float* __restrict__ nwg,
             const float* __restrict__ b1g,
             const float* __restrict__ gbg,
             const float* __restrict__ b2g,
             const float* __restrict__ tgg,
             const float* __restrict__ fgg,
             float* __restrict__ y,
             int N)
{
    extern __shared__ __align__(16) float sm[];
    float* s_g   = sm + S_G;
    float* s_h1  = sm + S_B1;
    float* s_tg  = sm + S_TG;
    float* s_fg  = sm + S_FG;
    float* s_gb  = sm + S_GB;
    float* s_bb1 = sm + S_BB1;
    float* s_bb2 = sm + S_BB2;
    float* s_nw  = sm + S_NW;
    float* s_red = sm + S_RED;

    const int tid  = threadIdx.x;
    const int lane = tid & 31;
    const int wrp  = tid >> 5;
    const int nodl = wrp >> 1;
    const int half = wrp & 1;

    for (int i = tid; i < 378; i += THREADS) s_tg[i] = tgg[i];
    for (int i = tid; i < 378; i += THREADS) s_fg[i] = fgg[i];
    if (tid < 256) s_gb[tid] = gbg[tid];
    if (tid < 128) { s_bb1[tid] = b1g[tid]; s_bb2[tid] = b2g[tid]; }
    if (tid < 384) s_nw[tid] = nwg[tid];

    const int node = blockIdx.x * NB + nodl;
    const bool valid = node < N;

    // ---------- Phase 0: load x, sumsq, pack + RMS-norm ----------
    float v[18];
    float ss = 0.f;
    if (valid) {
        const float* xr = x + (size_t)node * XW + half * 576;
#pragma unroll
        for (int k = 0; k < 18; k++) { v[k] = xr[lane + 32 * k]; ss += v[k] * v[k]; }
    } else {
#pragma unroll
        for (int k = 0; k < 18; k++) v[k] = 0.f;
    }
#pragma unroll
    for (int o = 16; o; o >>= 1) ss += __shfl_xor_sync(0xffffffffu, ss, o);
    if (lane == 0) s_red[wrp] = ss;
    __syncthreads();
    const float sst = s_red[nodl * 2] + s_red[nodl * 2 + 1];
    const float rinv = rsqrtf(sst * (1.0f / 1152.0f) + 1e-6f);

#pragma unroll
    for (int k = 0; k < 18; k++) {
        int j = half * 576 + lane + 32 * k;
        int l, coeff, c;
        if (j < 128)      { l = 0; coeff = 0; c = j; }
        else if (j < 512) { l = 1; int q = j - 128; c = q / 3; coeff = 1 + (q - 3 * c); }
        else              { l = 2; int q = j - 512; c = q / 5; coeff = 4 + (q - 5 * c); }
        s_g[(coeff * NB + nodl) * 128 + c] = v[k] * rinv * s_nw[l * 128 + c];
    }
    __syncthreads();

    // ---------- Phase 1: GEMM1 via mma ----------
    packA(s_g, 2304, tid);                       // 72*128 in place
    gemm_degree_mma((const u32*)s_g, g_w1_pack, s_h1, s_bb1, (u32*)(s_g + 10240));
    __syncthreads();

    // ---------- Phase 2: to_grid ----------
    {
        float4 h1r[MCO];
#pragma unroll
        for (int m = 0; m < MCO; m++)
            h1r[m] = ((const float4*)s_h1)[(m * NB + nodl) * 32 + lane];
        const int a0 = half * 21;
        for (int a = a0; a < a0 + 21; a++) {
            float4 acc = make_float4(0.f, 0.f, 0.f, 0.f);
#pragma unroll
            for (int m = 0; m < MCO; m++) {
                float t = s_tg[a * MCO + m];
                acc.x += t * h1r[m].x; acc.y += t * h1r[m].y;
                acc.z += t * h1r[m].z; acc.w += t * h1r[m].w;
            }
            ((float4*)s_g)[(nodl * AA + a) * 32 + lane] = acc;
        }
    }
    __syncthreads();

    // ---------- Phase 3+4: GEMM2 (336x256x128) via mma + SwiGLU ----------
    {
        u32* sgu  = (u32*)s_g;
        u32* bbuf = (u32*)s_h1;          // two 4096-u32 chunk slots

        packA(s_g, 10752, tid);          // 336*128 in place
        {   // stage chunk 0 (pure copy)
            const uint4* src = (const uint4*)g_gw_pack;
            uint4* dst = (uint4*)bbuf;
            for (int p = tid; p < 1024; p += THREADS) dst[p] = src[p];
        }
        __syncthreads();

        const int rt = (wrp < 14) ? (wrp % 7) : 0;
        const int ch = (wrp < 14) ? (wrp / 7) : 0;
        const int rr = rt * 16 + (lane >> 2);
        const int ks = (lane & 3) * 2;

        for (int b = 0; b < 3; b++) {
            const int rbase = b * 112;
            float4 c[16];
#pragma unroll
            for (int i = 0; i < 16; i++) c[i] = make_float4(0.f, 0.f, 0.f, 0.f);

            for (int kc = 0; kc < 8; kc++) {
                // prefetch next chunk (next block's chunk 0 at kc==7)
                const int nkc = (kc < 7) ? (kc + 1) : 0;
                if (kc < 7 || b < 2) {
                    const uint4* src = (const uint4*)(g_gw_pack + nkc * 4096);
                    uint4* dst = (uint4*)(bbuf + ((kc + 1) & 1) * 4096);
                    for (int p = tid; p < 1024; p += THREADS) dst[p] = src[p];
                }

                if (wrp < 14) {
                    const u32* Ar = sgu + (rbase + rr) * 128 + kc * 16 + ks;
                    u64 L0 = *(const u64*)(Ar);
                    u64 L1 = *(const u64*)(Ar + 8 * 128);
                    u64 L2 = *(const u64*)(Ar + 8);
                    u64 L3 = *(const u64*)(Ar + 8 * 128 + 8);
                    u32 ah0, ah1, ah2, ah3, al0, al1, al2, al3;
                    { u32 p0 = (u32)L0, p1 = (u32)(L0 >> 32); ah0 = prmt(p0, p1, 0x5410); al0 = prmt(p0, p1, 0x7632); }
                    { u32 p0 = (u32)L1, p1 = (u32)(L1 >> 32); ah1 = prmt(p0, p1, 0x5410); al1 = prmt(p0, p1, 0x7632); }
                    { u32 p0 = (u32)L2, p1 = (u32)(L2 >> 32); ah2 = prmt(p0, p1, 0x5410); al2 = prmt(p0, p1, 0x7632); }
                    { u32 p0 = (u32)L3, p1 = (u32)(L3 >> 32); ah3 = prmt(p0, p1, 0x5410); al3 = prmt(p0, p1, 0x7632); }

                    const u32* bu = bbuf + (kc & 1) * 4096;
                    const int jsel2 = 2 * (lane & 3);
#pragma unroll
                    for (int i = 0; i < 16; i++) {
                        const int nt = (i < 8) ? (ch * 8 + i) : (16 + ch * 8 + (i - 8));
                        const int n  = nt * 8 + (lane >> 2);
                        u64 H = *(const u64*)(bu + n * 8 + jsel2);
                        u64 L = *(const u64*)(bu + 2048 + n * 8 + jsel2);
                        u32 bh0 = (u32)H, bh1 = (u32)(H >> 32);
                        u32 bl0 = (u32)L, bl1 = (u32)(L >> 32);
                        mma_bf16(c[i], ah0, ah1, ah2, ah3, bh0, bh1);
                        mma_bf16(c[i], ah0, ah1, ah2, ah3, bl0, bl1);
                        mma_bf16(c[i], al0, al1, al2, al3, bh0, bh1);
                    }
                }
                __syncthreads();
            }

            // SwiGLU epilogue
            if (wrp < 14) {
                const int r0 = rbase + rr;
#pragma unroll
                for (int i = 0; i < 8; i++) {
                    const int h0 = ch * 64 + i * 8 + (lane & 3) * 2;
                    const float bz0 = s_gb[h0], bz1 = s_gb[h0 + 1];
                    const float bg0 = s_gb[128 + h0], bg1 = s_gb[128 + h0 + 1];
                    float4 z4 = c[i], g4 = c[i + 8];
                    float z0 = z4.x + bz0, z1 = z4.y + bz1;
                    float z2 = z4.z + bz0, z3 = z4.w + bz1;
                    float g0 = g4.x + bg0, g1 = g4.y + bg1;
                    float g2 = g4.z + bg0, g3 = g4.w + bg1;
                    float2 o01, o23;
                    o01.x = z0 * (1.f / (1.f + __expf(-z0))) * g0;
                    o01.y = z1 * (1.f / (1.f + __expf(-z1))) * g1;
                    o23.x = z2 * (1.f / (1.f + __expf(-z2))) * g2;
                    o23.y = z3 * (1.f / (1.f + __expf(-z3))) * g3;
                    *(float2*)(s_g + r0 * 128 + h0) = o01;
                    *(float2*)(s_g + (r0 + 8) * 128 + h0) = o23;
                }
            }
        }
    }
    __syncthreads();

    // ---------- Phase 5: from_grid ----------
    {
        const int m0   = half ? 5 : 0;
        const int mcnt = half ? 4 : 5;
        float4 acc[5];
#pragma unroll
        for (int m = 0; m < 5; m++) acc[m] = make_float4(0.f, 0.f, 0.f, 0.f);
        for (int a = 0; a < AA; a++) {
            float4 g4 = ((const float4*)s_g)[(nodl * AA + a) * 32 + lane];
#pragma unroll
            for (int m = 0; m < 5; m++) {
                if (m < mcnt) {
                    float f = s_fg[(m0 + m) * AA + a];
                    acc[m].x += f * g4.x; acc[m].y += f * g4.y;
                    acc[m].z += f * g4.z; acc[m].w += f * g4.w;
                }
            }
        }
#pragma unroll
        for (int m = 0; m < 5; m++)
            if (m < mcnt)
                ((float4*)s_h1)[((m0 + m) * NB + nodl) * 32 + lane] = acc[m];
    }
    __syncthreads();

    // ---------- Phase 6: GEMM3 via mma ----------
    packA(s_h1, 2304, tid);
    gemm_degree_mma((const u32*)s_h1, g_w2_pack, s_g, s_bb2, (u32*)(s_g + 10240));
    __syncthreads();

    // ---------- Phase 7: unpack + store ----------
    if (valid) {
        float* yr = y + (size_t)node * XW;
#pragma unroll
        for (int k = 0; k < 18; k++) {
            int j = half * 576 + lane + 32 * k;
            int coeff, c;
            if (j < 128)      { coeff = 0; c = j; }
            else if (j < 512) { int q = j - 128; c = q / 3; coeff = 1 + (q - 3 * c); }
            else              { int q = j - 512; c = q / 5; coeff = 4 + (q - 5 * c); }
            yr[j] = s_g[(coeff * NB + nodl) * 128 + c];
        }
    }
}

extern "C" void kernel_launch(void* const* d_in, const int* in_sizes, int n_in,
                              void* d_out, int out_size)
{
    const float* x   = (const float*)d_in[0];
    const float* nw  = (const float*)d_in[1];
    const float* w1  = (const float*)d_in[2];
    const float* b1  = (const float*)d_in[3];
    const float* gw  = (const float*)d_in[4];
    const float* gb  = (const float*)d_in[5];
    const float* b2  = (const float*)d_in[7];
    const float* tg  = (const float*)d_in[8];
    const float* fg  = (const float*)d_in[9];
    const float* w2  = (const float*)d_in[6];
    float* y = (float*)d_out;

    const int N = in_sizes[0] / XW;

    prep_kernel<<<128, 512>>>(gw, w1, w2);

    const int smem_bytes = SMEM_FLOATS * 4;
    cudaFuncSetAttribute(eqffn_kernel, cudaFuncAttributeMaxDynamicSharedMemorySize, smem_bytes);
    const int grid = (N + NB - 1) / NB;
    eqffn_kernel<<<grid, THREADS, smem_bytes>>>(x, nw, b1, gb, b2, tg, fg, y, N);
}

// round 10
// speedup vs baseline: 2.0286x; 1.2348x over previous
#include <cuda_runtime.h>
#include <cuda_bf16.h>

typedef unsigned long long u64;
typedef unsigned int u32;

// ---------------- mma.sync bf16 helpers ----------------
__device__ __forceinline__ u32 prmt(u32 a, u32 b, u32 s) {
    u32 d; asm("prmt.b32 %0, %1, %2, %3;" : "=r"(d) : "r"(a), "r"(b), "r"(s));
    return d;
}
__device__ __forceinline__ void mma_bf16(float4& c, u32 a0, u32 a1, u32 a2, u32 a3,
                                         u32 b0, u32 b1) {
    asm("mma.sync.aligned.m16n8k16.row.col.f32.bf16.bf16.f32 "
        "{%0,%1,%2,%3}, {%4,%5,%6,%7}, {%8,%9}, {%0,%1,%2,%3};"
        : "+f"(c.x), "+f"(c.y), "+f"(c.z), "+f"(c.w)
        : "r"(a0), "r"(a1), "r"(a2), "r"(a3), "r"(b0), "r"(b1));
}
// fp32 -> {bf16 hi (low16), bf16 lo (high16)} packed u32
__device__ __forceinline__ u32 pack_hl(float a) {
    __nv_bfloat16 hb = __float2bfloat16_rn(a);
    float r = a - __bfloat162float(hb);
    __nv_bfloat16 lb = __float2bfloat16_rn(r);
    return (u32)__bfloat16_as_ushort(hb) | ((u32)__bfloat16_as_ushort(lb) << 16);
}
__device__ __forceinline__ void split_pair(float2 w, u32& hiw, u32& low) {
    __nv_bfloat16 h0 = __float2bfloat16_rn(w.x);
    __nv_bfloat16 h1 = __float2bfloat16_rn(w.y);
    float r0 = w.x - __bfloat162float(h0);
    float r1 = w.y - __bfloat162float(h1);
    __nv_bfloat16 l0 = __float2bfloat16_rn(r0);
    __nv_bfloat16 l1 = __float2bfloat16_rn(r1);
    hiw = (u32)__bfloat16_as_ushort(h0) | ((u32)__bfloat16_as_ushort(h1) << 16);
    low = (u32)__bfloat16_as_ushort(l0) | ((u32)__bfloat16_as_ushort(l1) << 16);
}
__device__ __forceinline__ u32 smem_u32(const void* p) {
    u32 a; asm("{ .reg .u64 t; cvta.to.shared.u64 t, %1; cvt.u32.u64 %0, t; }" : "=r"(a) : "l"(p));
    return a;
}
__device__ __forceinline__ void cp16(u32 dst, const void* src) {
    asm volatile("cp.async.cg.shared.global [%0], [%1], 16;" :: "r"(dst), "l"(src));
}
#define CP_COMMIT() asm volatile("cp.async.commit_group;" ::: "memory")
#define CP_WAIT0()  asm volatile("cp.async.wait_group 0;" ::: "memory")

// ---------------- problem constants ----------------
#define NB   8
#define MCO  9
#define AA   42
#define XW   1152
#define THREADS 512

// ---------------- prepacked weights (filled by prep_kernel) ----------------
__device__ u32 g_gw_pack[8 * 4096];   // grid_w: [8 kc][hi:2048 | lo:2048]
__device__ u32 g_w1_pack[8 * 6144];   // w1: [8 kc][hi:3072 | lo:3072], n=deg*128+h
__device__ u32 g_w2_pack[8 * 6144];

// ---------------- shared memory layout (floats) ----------------
#define S_G    0                    // 336*128 (g/gg/out; rows 80+ alias W staging for GEMM1/3)
#define S_B1   43008                // 72*128 (h1/h2); GEMM2 B staging aliases (8192 u32)
#define S_TG   56320
#define S_FG   (S_TG + 378)
#define S_GB   (S_FG + 378)
#define S_BB1  (S_GB + 256)
#define S_BB2  (S_BB1 + 128)
#define S_NW   (S_BB2 + 128)
#define S_RED  (S_NW + 384)
#define SMEM_FLOATS (S_RED + 16)

// ---------------- prep kernel: convert weights once ----------------
extern "C" __global__ void prep_kernel(const float* __restrict__ gw,
                                       const float* __restrict__ w1,
                                       const float* __restrict__ w2)
{
    const int t = blockIdx.x * blockDim.x + threadIdx.x;
    const int stride = gridDim.x * blockDim.x;
    for (int p = t; p < 16384; p += stride) {
        int n = p >> 6, kc = (p >> 3) & 7, j = p & 7;
        float2 w = *(const float2*)(gw + n * 128 + kc * 16 + 2 * j);
        u32 hiw, low; split_pair(w, hiw, low);
        int pos = 2 * (j & 3) + (j >> 2);
        g_gw_pack[kc * 4096 + n * 8 + pos] = hiw;
        g_gw_pack[kc * 4096 + 2048 + n * 8 + pos] = low;
    }
    for (int p = t; p < 24576; p += stride) {
        int n = p >> 6, kc = (p >> 3) & 7, j = p & 7;
        int pos = 2 * (j & 3) + (j >> 2);
        {
            float2 w = *(const float2*)(w1 + n * 128 + kc * 16 + 2 * j);
            u32 hiw, low; split_pair(w, hiw, low);
            g_w1_pack[kc * 6144 + n * 8 + pos] = hiw;
            g_w1_pack[kc * 6144 + 3072 + n * 8 + pos] = low;
        }
        {
            float2 w = *(const float2*)(w2 + n * 128 + kc * 16 + 2 * j);
            u32 hiw, low; split_pair(w, hiw, low);
            g_w2_pack[kc * 6144 + n * 8 + pos] = hiw;
            g_w2_pack[kc * 6144 + 3072 + n * 8 + pos] = low;
        }
    }
}

// ---------------- GEMM1/GEMM3: per-degree 72x128x128 via mma.sync ----------------
// Apk: packed A (72 rows x 128 u32). wpk: prepacked weights. O: fp32 72x128.
// wbuf: smem staging 2*6144 u32 (cp.async double-buffered).
__device__ __forceinline__ void gemm_degree_mma(const u32* __restrict__ Apk,
                                                const u32* __restrict__ wpk,
                                                float* __restrict__ O,
                                                const float* __restrict__ bias0,
                                                u32* __restrict__ wbuf)
{
    const int tid  = threadIdx.x;
    const int lane = tid & 31;
    const int wrp  = tid >> 5;
    const u32 wbuf_addr = smem_u32(wbuf);

    // prologue: issue chunk 0 into buffer 0
    for (int p = tid; p < 1536; p += THREADS)
        cp16(wbuf_addr + p * 16, ((const uint4*)wpk) + p);
    CP_COMMIT();

    const int tile = (wrp < 12) ? (wrp >> 1) : 0;
    const int nh   = wrp & 1;
    int trow, tval, tdeg;
    if (tile == 0)      { trow = 0;                 tval = 8;                  tdeg = 0; }
    else if (tile <= 2) { trow = 8 + 16 * (tile - 1);  tval = (tile == 1) ? 16 : 8;  tdeg = 1; }
    else                { trow = 32 + 16 * (tile - 3); tval = (tile == 5) ? 8 : 16;  tdeg = 2; }

    float4 c[8];
#pragma unroll
    for (int i = 0; i < 8; i++) c[i] = make_float4(0.f, 0.f, 0.f, 0.f);

    const int r0 = trow + (lane >> 2);
    const u32* Ar = Apk + r0 * 128 + (lane & 3) * 2;
    const int bbase = (tdeg * 128 + nh * 64) * 8 + 2 * (lane & 3);

    for (int kc = 0; kc < 8; kc++) {
        CP_WAIT0();
        __syncthreads();
        if (kc < 7) {
            const uint4* src = (const uint4*)(wpk + (kc + 1) * 6144);
            const u32 dstb = wbuf_addr + ((kc + 1) & 1) * 24576;
            for (int p = tid; p < 1536; p += THREADS)
                cp16(dstb + p * 16, src + p);
            CP_COMMIT();
        }
        if (wrp < 12) {
            const u32* a = Ar + kc * 16;
            u64 L0 = *(const u64*)(a);
            u64 L1 = *(const u64*)(a + 8 * 128);
            u64 L2 = *(const u64*)(a + 8);
            u64 L3 = *(const u64*)(a + 8 * 128 + 8);
            u32 ah0, ah1, ah2, ah3, al0, al1, al2, al3;
            { u32 p0 = (u32)L0, p1 = (u32)(L0 >> 32); ah0 = prmt(p0, p1, 0x5410); al0 = prmt(p0, p1, 0x7632); }
            { u32 p0 = (u32)L1, p1 = (u32)(L1 >> 32); ah1 = prmt(p0, p1, 0x5410); al1 = prmt(p0, p1, 0x7632); }
            { u32 p0 = (u32)L2, p1 = (u32)(L2 >> 32); ah2 = prmt(p0, p1, 0x5410); al2 = prmt(p0, p1, 0x7632); }
            { u32 p0 = (u32)L3, p1 = (u32)(L3 >> 32); ah3 = prmt(p0, p1, 0x5410); al3 = prmt(p0, p1, 0x7632); }

            const u32* bu = wbuf + (kc & 1) * 6144 + bbase;
#pragma unroll
            for (int i = 0; i < 8; i++) {
                const int noff = (i * 8 + (lane >> 2)) * 8;
                u64 H = *(const u64*)(bu + noff);
                u64 L = *(const u64*)(bu + 3072 + noff);
                u32 bh0 = (u32)H, bh1 = (u32)(H >> 32);
                u32 bl0 = (u32)L, bl1 = (u32)(L >> 32);
                mma_bf16(c[i], ah0, ah1, ah2, ah3, bh0, bh1);
                mma_bf16(c[i], ah0, ah1, ah2, ah3, bl0, bl1);
                mma_bf16(c[i], al0, al1, al2, al3, bh0, bh1);
            }
        }
    }

    if (wrp < 12) {
        const bool wr0 = (lane >> 2) < tval;
        const bool wr1 = (lane >> 2) + 8 < tval;
#pragma unroll
        for (int i = 0; i < 8; i++) {
            const int col = nh * 64 + i * 8 + 2 * (lane & 3);
            float2 o0 = make_float2(c[i].x, c[i].y);
            float2 o1 = make_float2(c[i].z, c[i].w);
            if (tile == 0) {
                float b0 = bias0[col], b1 = bias0[col + 1];
                o0.x += b0; o0.y += b1;
                o1.x += b0; o1.y += b1;
            }
            if (wr0) *(float2*)(O + r0 * 128 + col) = o0;
            if (wr1) *(float2*)(O + (r0 + 8) * 128 + col) = o1;
        }
    }
}

extern "C" __global__ void __launch_bounds__(THREADS, 1)
eqffn_kernel(const float* __restrict__ x,
             const float* __restrict__ nwg,
             const float* __restrict__ b1g,
             const float* __restrict__ gbg,
             const float* __restrict__ b2g,
             const float* __restrict__ tgg,
             const float* __restrict__ fgg,
             float* __restrict__ y,
             int N)
{
    extern __shared__ __align__(16) float sm[];
    float* s_g   = sm + S_G;
    float* s_h1  = sm + S_B1;
    float* s_tg  = sm + S_TG;
    float* s_fg  = sm + S_FG;
    float* s_gb  = sm + S_GB;
    float* s_bb1 = sm + S_BB1;
    float* s_bb2 = sm + S_BB2;
    float* s_nw  = sm + S_NW;
    float* s_red = sm + S_RED;

    const int tid  = threadIdx.x;
    const int lane = tid & 31;
    const int wrp  = tid >> 5;
    const int nodl = wrp >> 1;
    const int half = wrp & 1;

    for (int i = tid; i < 378; i += THREADS) s_tg[i] = tgg[i];
    for (int i = tid; i < 378; i += THREADS) s_fg[i] = fgg[i];
    if (tid < 256) s_gb[tid] = gbg[tid];
    if (tid < 128) { s_bb1[tid] = b1g[tid]; s_bb2[tid] = b2g[tid]; }
    if (tid < 384) s_nw[tid] = nwg[tid];

    const int node = blockIdx.x * NB + nodl;
    const bool valid = node < N;

    // ---------- Phase 0: load x, sumsq, RMS-norm, write PACKED A for GEMM1 ----------
    float v[18];
    float ss = 0.f;
    if (valid) {
        const float* xr = x + (size_t)node * XW + half * 576;
#pragma unroll
        for (int k = 0; k < 18; k++) { v[k] = xr[lane + 32 * k]; ss += v[k] * v[k]; }
    } else {
#pragma unroll
        for (int k = 0; k < 18; k++) v[k] = 0.f;
    }
#pragma unroll
    for (int o = 16; o; o >>= 1) ss += __shfl_xor_sync(0xffffffffu, ss, o);
    if (lane == 0) s_red[wrp] = ss;
    __syncthreads();
    const float sst = s_red[nodl * 2] + s_red[nodl * 2 + 1];
    const float rinv = rsqrtf(sst * (1.0f / 1152.0f) + 1e-6f);

#pragma unroll
    for (int k = 0; k < 18; k++) {
        int j = half * 576 + lane + 32 * k;
        int l, coeff, c;
        if (j < 128)      { l = 0; coeff = 0; c = j; }
        else if (j < 512) { l = 1; int q = j - 128; c = q / 3; coeff = 1 + (q - 3 * c); }
        else              { l = 2; int q = j - 512; c = q / 5; coeff = 4 + (q - 5 * c); }
        ((u32*)s_g)[(coeff * NB + nodl) * 128 + c] = pack_hl(v[k] * rinv * s_nw[l * 128 + c]);
    }
    __syncthreads();

    // ---------- Phase 1: GEMM1 via mma (A already packed) ----------
    gemm_degree_mma((const u32*)s_g, g_w1_pack, s_h1, s_bb1, (u32*)(s_g + 10240));
    __syncthreads();

    // ---------- Phase 2: to_grid -> write PACKED A for GEMM2 ----------
    {
        float4 h1r[MCO];
#pragma unroll
        for (int m = 0; m < MCO; m++)
            h1r[m] = ((const float4*)s_h1)[(m * NB + nodl) * 32 + lane];
        const int a0 = half * 21;
        for (int a = a0; a < a0 + 21; a++) {
            float4 acc = make_float4(0.f, 0.f, 0.f, 0.f);
#pragma unroll
            for (int m = 0; m < MCO; m++) {
                float t = s_tg[a * MCO + m];
                acc.x += t * h1r[m].x; acc.y += t * h1r[m].y;
                acc.z += t * h1r[m].z; acc.w += t * h1r[m].w;
            }
            uint4 pk;
            pk.x = pack_hl(acc.x); pk.y = pack_hl(acc.y);
            pk.z = pack_hl(acc.z); pk.w = pack_hl(acc.w);
            ((uint4*)s_g)[(nodl * AA + a) * 32 + lane] = pk;
        }
    }
    __syncthreads();

    // ---------- Phase 3+4: GEMM2 (336x256x128) via mma + SwiGLU ----------
    {
        u32* sgu  = (u32*)s_g;
        u32* bbuf = (u32*)s_h1;
        const u32 bbuf_addr = smem_u32(bbuf);

        // prologue: issue chunk 0
        for (int p = tid; p < 1024; p += THREADS)
            cp16(bbuf_addr + p * 16, ((const uint4*)g_gw_pack) + p);
        CP_COMMIT();

        const int rt = (wrp < 14) ? (wrp % 7) : 0;
        const int ch = (wrp < 14) ? (wrp / 7) : 0;
        const int rr = rt * 16 + (lane >> 2);
        const int ks = (lane & 3) * 2;

        for (int b = 0; b < 3; b++) {
            const int rbase = b * 112;
            float4 c[16];
#pragma unroll
            for (int i = 0; i < 16; i++) c[i] = make_float4(0.f, 0.f, 0.f, 0.f);

            for (int kc = 0; kc < 8; kc++) {
                CP_WAIT0();
                __syncthreads();
                const int g = b * 8 + kc;
                if (g < 23) {
                    const int nkc = (kc + 1) & 7;
                    const uint4* src = (const uint4*)(g_gw_pack + nkc * 4096);
                    const u32 dstb = bbuf_addr + ((g + 1) & 1) * 16384;
                    for (int p = tid; p < 1024; p += THREADS)
                        cp16(dstb + p * 16, src + p);
                    CP_COMMIT();
                }

                if (wrp < 14) {
                    const u32* Ar = sgu + (rbase + rr) * 128 + kc * 16 + ks;
                    u64 L0 = *(const u64*)(Ar);
                    u64 L1 = *(const u64*)(Ar + 8 * 128);
                    u64 L2 = *(const u64*)(Ar + 8);
                    u64 L3 = *(const u64*)(Ar + 8 * 128 + 8);
                    u32 ah0, ah1, ah2, ah3, al0, al1, al2, al3;
                    { u32 p0 = (u32)L0, p1 = (u32)(L0 >> 32); ah0 = prmt(p0, p1, 0x5410); al0 = prmt(p0, p1, 0x7632); }
                    { u32 p0 = (u32)L1, p1 = (u32)(L1 >> 32); ah1 = prmt(p0, p1, 0x5410); al1 = prmt(p0, p1, 0x7632); }
                    { u32 p0 = (u32)L2, p1 = (u32)(L2 >> 32); ah2 = prmt(p0, p1, 0x5410); al2 = prmt(p0, p1, 0x7632); }
                    { u32 p0 = (u32)L3, p1 = (u32)(L3 >> 32); ah3 = prmt(p0, p1, 0x5410); al3 = prmt(p0, p1, 0x7632); }

                    const u32* bu = bbuf + (g & 1) * 4096;
                    const int jsel2 = 2 * (lane & 3);
#pragma unroll
                    for (int i = 0; i < 16; i++) {
                        const int nt = (i < 8) ? (ch * 8 + i) : (16 + ch * 8 + (i - 8));
                        const int n  = nt * 8 + (lane >> 2);
                        u64 H = *(const u64*)(bu + n * 8 + jsel2);
                        u64 L = *(const u64*)(bu + 2048 + n * 8 + jsel2);
                        u32 bh0 = (u32)H, bh1 = (u32)(H >> 32);
                        u32 bl0 = (u32)L, bl1 = (u32)(L >> 32);
                        mma_bf16(c[i], ah0, ah1, ah2, ah3, bh0, bh1);
                        mma_bf16(c[i], ah0, ah1, ah2, ah3, bl0, bl1);
                        mma_bf16(c[i], al0, al1, al2, al3, bh0, bh1);
                    }
                }
            }
            __syncthreads();   // all MMA reads of this block's A rows done before epilogue writes

            if (wrp < 14) {
                const int r0 = rbase + rr;
#pragma unroll
                for (int i = 0; i < 8; i++) {
                    const int h0 = ch * 64 + i * 8 + (lane & 3) * 2;
                    const float bz0 = s_gb[h0], bz1 = s_gb[h0 + 1];
                    const float bg0 = s_gb[128 + h0], bg1 = s_gb[128 + h0 + 1];
                    float4 z4 = c[i], g4 = c[i + 8];
                    float z0 = z4.x + bz0, z1 = z4.y + bz1;
                    float z2 = z4.z + bz0, z3 = z4.w + bz1;
                    float g0 = g4.x + bg0, g1 = g4.y + bg1;
                    float g2 = g4.z + bg0, g3 = g4.w + bg1;
                    float2 o01, o23;
                    o01.x = z0 * (1.f / (1.f + __expf(-z0))) * g0;
                    o01.y = z1 * (1.f / (1.f + __expf(-z1))) * g1;
                    o23.x = z2 * (1.f / (1.f + __expf(-z2))) * g2;
                    o23.y = z3 * (1.f / (1.f + __expf(-z3))) * g3;
                    *(float2*)(s_g + r0 * 128 + h0) = o01;
                    *(float2*)(s_g + (r0 + 8) * 128 + h0) = o23;
                }
            }
        }
    }
    __syncthreads();

    // ---------- Phase 5: from_grid -> write PACKED A for GEMM3 ----------
    {
        const int m0   = half ? 5 : 0;
        const int mcnt = half ? 4 : 5;
        float4 acc[5];
#pragma unroll
        for (int m = 0; m < 5; m++) acc[m] = make_float4(0.f, 0.f, 0.f, 0.f);
        for (int a = 0; a < AA; a++) {
            float4 g4 = ((const float4*)s_g)[(nodl * AA + a) * 32 + lane];
#pragma unroll
            for (int m = 0; m < 5; m++) {
                if (m < mcnt) {
                    float f = s_fg[(m0 + m) * AA + a];
                    acc[m].x += f * g4.x; acc[m].y += f * g4.y;
                    acc[m].z += f * g4.z; acc[m].w += f * g4.w;
                }
            }
        }
#pragma unroll
        for (int m = 0; m < 5; m++)
            if (m < mcnt) {
                uint4 pk;
                pk.x = pack_hl(acc[m].x); pk.y = pack_hl(acc[m].y);
                pk.z = pack_hl(acc[m].z); pk.w = pack_hl(acc[m].w);
                ((uint4*)s_h1)[((m0 + m) * NB + nodl) * 32 + lane] = pk;
            }
    }
    __syncthreads();

    // ---------- Phase 6: GEMM3 via mma ----------
    gemm_degree_mma((const u32*)s_h1, g_w2_pack, s_g, s_bb2, (u32*)(s_g + 10240));
    __syncthreads();

    // ---------- Phase 7: unpack + store ----------
    if (valid) {
        float* yr = y + (size_t)node * XW;
#pragma unroll
        for (int k = 0; k < 18; k++) {
            int j = half * 576 + lane + 32 * k;
            int coeff, c;
            if (j < 128)      { coeff = 0; c = j; }
            else if (j < 512) { int q = j - 128; c = q / 3; coeff = 1 + (q - 3 * c); }
            else              { int q = j - 512; c = q / 5; coeff = 4 + (q - 5 * c); }
            yr[j] = s_g[(coeff * NB + nodl) * 128 + c];
        }
    }
}

extern "C" void kernel_launch(void* const* d_in, const int* in_sizes, int n_in,
                              void* d_out, int out_size)
{
    const float* x   = (const float*)d_in[0];
    const float* nw  = (const float*)d_in[1];
    const float* w1  = (const float*)d_in[2];
    const float* b1  = (const float*)d_in[3];
    const float* gw  = (const float*)d_in[4];
    const float* gb  = (const float*)d_in[5];
    const float* w2  = (const float*)d_in[6];
    const float* b2  = (const float*)d_in[7];
    const float* tg  = (const float*)d_in[8];
    const float* fg  = (const float*)d_in[9];
    float* y = (float*)d_out;

    const int N = in_sizes[0] / XW;

    prep_kernel<<<128, 512>>>(gw, w1, w2);

    const int smem_bytes = SMEM_FLOATS * 4;
    cudaFuncSetAttribute(eqffn_kernel, cudaFuncAttributeMaxDynamicSharedMemorySize, smem_bytes);
    const int grid = (N + NB - 1) / NB;
    eqffn_kernel<<<grid, THREADS, smem_bytes>>>(x, nw, b1, gb, b2, tg, fg, y, N);
}